// round 15
// baseline (speedup 1.0000x reference)
#include <cuda_runtime.h>
#include <cuda_fp16.h>
#include <cuda_fp8.h>
#include <cstdint>
#include <cfloat>
#include <math.h>

#define Bn 2
#define Ln 4096
#define Hn 8
#define Dn 64
#define NTOP 45
#define NSAMP 45
#define NCAND 160
#define BHn (Bn*Hn)
#define SPLITS 64
#define SUB 64
#define AWARPS 6
#define ATHREADS (AWARPS*32)

typedef unsigned long long ull;

__device__ __forceinline__ ull pk2(float x, float y) {
    ull r; asm("mov.b64 %0, {%1, %2};" : "=l"(r) : "f"(x), "f"(y)); return r;
}
__device__ __forceinline__ void upk2(float& x, float& y, ull v) {
    asm("mov.b64 {%0, %1}, %2;" : "=f"(x), "=f"(y) : "l"(v));
}
__device__ __forceinline__ void ffma2(ull& acc, ull a, ull b) {
    asm("fma.rn.f32x2 %0, %1, %2, %3;" : "=l"(acc) : "l"(a), "l"(b), "l"(acc));
}

// ---------------- device scratch ----------------
__device__ float    g_M[BHn * Ln];
__device__ int      g_cand[BHn * NCAND];
__device__ float    g_Mex[BHn * NCAND];
__device__ int      g_top[BHn * NTOP];
__device__ unsigned g_anyodd = 0u;
__device__ unsigned g_Kf8[(size_t)Bn*Ln*Hn*Dn/4];   // e4m3 copy of K, 4 MB
__device__ float    g_pl [BHn * NTOP * SPLITS];
__device__ float    g_pacc[(size_t)BHn * NTOP * SPLITS * Dn];  // 11.8 MB

// ---------------- K -> fp8 copy + index dtype detect (fused) ----------------
__global__ __launch_bounds__(256) void k_init(const float* __restrict__ k,
                                              const unsigned* __restrict__ raw) {
    int i = blockIdx.x * 256 + threadIdx.x;
    float4 f0 = ((const float4*)k)[2*i];
    float4 f1 = ((const float4*)k)[2*i+1];
    unsigned s0 = __nv_cvt_float2_to_fp8x2(make_float2(f0.x,f0.y), __NV_SATFINITE, __NV_E4M3);
    unsigned s1 = __nv_cvt_float2_to_fp8x2(make_float2(f0.z,f0.w), __NV_SATFINITE, __NV_E4M3);
    unsigned s2 = __nv_cvt_float2_to_fp8x2(make_float2(f1.x,f1.y), __NV_SATFINITE, __NV_E4M3);
    unsigned s3 = __nv_cvt_float2_to_fp8x2(make_float2(f1.z,f1.w), __NV_SATFINITE, __NV_E4M3);
    *(uint2*)&g_Kf8[2*i] = make_uint2(s0 | (s1 << 16), s2 | (s3 << 16));

    if (blockIdx.x < 90) {
        unsigned v = 0;
        for (int j = 1 + 2*i; j < Ln*NSAMP; j += 2*90*256) v |= raw[j];
        #pragma unroll
        for (int o = 16; o; o >>= 1) v |= __shfl_xor_sync(0xffffffffu, v, o);
        if ((threadIdx.x & 31) == 0 && v) atomicOr(&g_anyodd, v);
    }
}

// ---------------- stage 1: fp8 screen, one warp = (b,l) x all 8 heads ----------------
__global__ __launch_bounds__(256) void k_scoreM(const float* __restrict__ q,
                                                const unsigned* __restrict__ raw) {
    int w    = (blockIdx.x * 256 + threadIdx.x) >> 5;
    int lane = threadIdx.x & 31;
    int head = lane >> 2;
    int quad = lane & 3;
    int b = w / Ln, l = w % Ln;

    const float4* qp = (const float4*)(q + (((size_t)b*Ln + l)*Hn + head)*Dn + quad*16);
    half2 qh[8];
    #pragma unroll
    for (int j = 0; j < 4; j++) {
        float4 f = qp[j];
        qh[2*j]   = __floats2half2_rn(f.x, f.y);
        qh[2*j+1] = __floats2half2_rn(f.z, f.w);
    }

    int sh = (g_anyodd == 0u) ? 1 : 0;
    const unsigned* ip = raw + ((size_t)(l * NSAMP) << sh);
    int i0 = (int)ip[(unsigned)lane << sh];
    int i1 = (lane < NSAMP - 32) ? (int)ip[(unsigned)(32 + lane) << sh] : 0;

    const uint4* kb = (const uint4*)g_Kf8 + (size_t)b * (Ln * 32);

    float mx = -FLT_MAX, sm = 0.f;
    #pragma unroll 9
    for (int s = 0; s < NSAMP; s++) {
        int id = __shfl_sync(0xffffffffu, (s < 32) ? i0 : i1, s & 31);
        uint4 kw = __ldg(kb + (id << 5) + lane);
        half2 acc;
        {
            __half2_raw h;
            h = __nv_cvt_fp8x2_to_halfraw2((__nv_fp8x2_storage_t)(kw.x & 0xffff), __NV_E4M3);
            acc = __hmul2(*(half2*)&h, qh[0]);
            h = __nv_cvt_fp8x2_to_halfraw2((__nv_fp8x2_storage_t)(kw.x >> 16), __NV_E4M3);
            acc = __hfma2(*(half2*)&h, qh[1], acc);
            h = __nv_cvt_fp8x2_to_halfraw2((__nv_fp8x2_storage_t)(kw.y & 0xffff), __NV_E4M3);
            acc = __hfma2(*(half2*)&h, qh[2], acc);
            h = __nv_cvt_fp8x2_to_halfraw2((__nv_fp8x2_storage_t)(kw.y >> 16), __NV_E4M3);
            acc = __hfma2(*(half2*)&h, qh[3], acc);
            h = __nv_cvt_fp8x2_to_halfraw2((__nv_fp8x2_storage_t)(kw.z & 0xffff), __NV_E4M3);
            acc = __hfma2(*(half2*)&h, qh[4], acc);
            h = __nv_cvt_fp8x2_to_halfraw2((__nv_fp8x2_storage_t)(kw.z >> 16), __NV_E4M3);
            acc = __hfma2(*(half2*)&h, qh[5], acc);
            h = __nv_cvt_fp8x2_to_halfraw2((__nv_fp8x2_storage_t)(kw.w & 0xffff), __NV_E4M3);
            acc = __hfma2(*(half2*)&h, qh[6], acc);
            h = __nv_cvt_fp8x2_to_halfraw2((__nv_fp8x2_storage_t)(kw.w >> 16), __NV_E4M3);
            acc = __hfma2(*(half2*)&h, qh[7], acc);
        }
        float d = __low2float(acc) + __high2float(acc);
        d += __shfl_xor_sync(0xffffffffu, d, 1);
        d += __shfl_xor_sync(0xffffffffu, d, 2);
        mx = fmaxf(mx, d);
        sm += d;
    }
    if (quad == 0)
        g_M[(b*Hn + head)*Ln + l] = mx - sm * (1.0f / (float)Ln);
}

// ---------------- stage 2a: top-160 candidates via radix-256 select ----------------
__global__ __launch_bounds__(1024) void k_cand(int bh0) {
    int bh  = bh0 + blockIdx.x;
    int tid = threadIdx.x;
    int lane = tid & 31;

    __shared__ int bins[256];
    __shared__ int ssum[256];
    __shared__ int s_sel, s_need, s_out;

    unsigned r[4];
    #pragma unroll
    for (int i = 0; i < 4; i++) {
        unsigned u = __float_as_uint(g_M[bh*Ln + tid + i*1024]);
        r[i] = (u & 0x80000000u) ? ~u : (u | 0x80000000u);
    }

    unsigned prefix = 0;
    int need = NCAND;
    #pragma unroll
    for (int p = 0; p < 4; p++) {
        int shift = 24 - 8*p;
        unsigned pmask = (p == 0) ? 0u : (0xFFFFFFFFu << (32 - 8*p));
        if (tid < 256) bins[tid] = 0;
        __syncthreads();
        #pragma unroll
        for (int i = 0; i < 4; i++)
            if ((r[i] & pmask) == prefix)
                atomicAdd(&bins[(r[i] >> shift) & 255], 1);
        __syncthreads();
        if (tid < 32) {
            int x[8], loc = 0;
            #pragma unroll
            for (int j = 0; j < 8; j++) { x[j] = bins[lane*8 + j]; loc += x[j]; }
            int suf = loc;
            #pragma unroll
            for (int o = 1; o < 32; o <<= 1) {
                int t = __shfl_down_sync(0xffffffffu, suf, o);
                if (lane + o < 32) suf += t;
            }
            int run = suf - loc;
            #pragma unroll
            for (int j = 7; j >= 0; j--) { run += x[j]; ssum[lane*8 + j] = run; }
        }
        __syncthreads();
        if (tid < 256) {
            int above = (tid < 255) ? ssum[tid + 1] : 0;
            if (ssum[tid] >= need && above < need) { s_sel = tid; s_need = need - above; }
        }
        __syncthreads();
        prefix |= ((unsigned)s_sel) << shift;
        need    = s_need;
        __syncthreads();
    }
    unsigned T = prefix;

    if (tid == 0) s_out = 0;
    __syncthreads();
    #pragma unroll
    for (int i = 0; i < 4; i++)
        if (r[i] > T) {
            int p = atomicAdd(&s_out, 1);
            g_cand[bh*NCAND + p] = tid + i*1024;
        }
    __syncthreads();
    #pragma unroll
    for (int i = 0; i < 4; i++)
        if (r[i] == T) {
            int p = atomicAdd(&s_out, 1);
            if (p < NCAND) g_cand[bh*NCAND + p] = tid + i*1024;
        }
}

// ---------------- stage 2b: exact fp32 rescore, 2 warps per candidate ----------------
__global__ __launch_bounds__(256) void k_rescore(const float* __restrict__ q,
                                                 const float* __restrict__ k,
                                                 const unsigned* __restrict__ raw,
                                                 int bh0) {
    int wp   = (blockIdx.x * 256 + threadIdx.x) >> 5;
    int lane = threadIdx.x & 31;
    int c2   = wp >> 1;
    int half = wp & 1;
    int grp  = lane >> 4;
    int sub  = lane & 15;
    int bh = bh0 + c2 / NCAND;
    int c  = c2 % NCAND;
    int b = bh / Hn, h = bh % Hn;
    int l = g_cand[bh*NCAND + c];

    const float4 qv = *((const float4*)(q + (((size_t)b*Ln + l)*Hn + h)*Dn) + sub);

    int sh = (g_anyodd == 0u) ? 1 : 0;
    const unsigned* ip = raw + ((size_t)(l * NSAMP) << sh);
    int base_s = half * 23;
    int ii = (lane < 23 && base_s + lane < NSAMP)
           ? (int)ip[(unsigned)(base_s + lane) << sh] : 0;

    const float4* kbase = (const float4*)(k + ((size_t)b*Ln*Hn + h)*Dn);

    float mx = -FLT_MAX, sm = 0.f;
    #pragma unroll
    for (int t = 0; t < 12; t++) {
        int sl = 2*t + grp;
        int id = __shfl_sync(0xffffffffu, ii, sl & 31);
        float4 kv = __ldg(kbase + (size_t)id*(Hn*Dn/4) + sub);
        float d = qv.x*kv.x + qv.y*kv.y + qv.z*kv.z + qv.w*kv.w;
        #pragma unroll
        for (int o = 1; o < 16; o <<= 1) d += __shfl_xor_sync(0xffffffffu, d, o);
        if (sl < 23 && base_s + sl < NSAMP) { mx = fmaxf(mx, d); sm += d; }
    }
    mx = fmaxf(mx, __shfl_xor_sync(0xffffffffu, mx, 16));
    sm += __shfl_xor_sync(0xffffffffu, sm, 16);

    __shared__ float2 s_part[8];
    int wloc = threadIdx.x >> 5;
    if (lane == 0) s_part[wloc] = make_float2(mx, sm);
    __syncthreads();
    if (half == 0 && lane == 0) {
        float2 o = s_part[wloc ^ 1];
        mx = fmaxf(mx, o.x);
        sm += o.y;
        g_Mex[bh*NCAND + c] = mx - sm * (1.0f / (float)Ln);
    }
}

// ---------------- stage 2c: exact top-45 of 160 (jax tie-break) ----------------
__global__ __launch_bounds__(NCAND) void k_sel45(int bh0) {
    int bh  = bh0 + blockIdx.x;
    int tid = threadIdx.x;
    __shared__ unsigned long long comp[NCAND];

    int idx = g_cand[bh*NCAND + tid];
    unsigned u = __float_as_uint(g_Mex[bh*NCAND + tid]);
    u = (u & 0x80000000u) ? ~u : (u | 0x80000000u);
    comp[tid] = ((unsigned long long)u << 32) | (unsigned)(Ln - 1 - idx);
    __syncthreads();

    unsigned long long mine = comp[tid];
    int rank = 0;
    #pragma unroll 16
    for (int j = 0; j < NCAND; j++) rank += (comp[j] > mine);
    if (rank < NTOP) g_top[bh*NTOP + rank] = idx;
}

// ---------------- stage 3: split-KV attention, 64 keys/block, FFMA2 ----------------
__global__ __launch_bounds__(ATHREADS, 5) void k_attn(const float* __restrict__ q,
                                                      const float* __restrict__ k,
                                                      const float* __restrict__ v,
                                                      int bh0) {
    int split = blockIdx.x;
    int bh    = bh0 + blockIdx.y;
    int b = bh / Hn, h = bh % Hn;
    int tid = threadIdx.x, warp = tid >> 5, lane = tid & 31;

    __shared__ __align__(16) float Ktpf[Dn * SUB];
    __shared__ __align__(16) float2 Vs2[SUB * 32];
    __shared__ __align__(16) float  Qt[Dn * 48];
    ull* ps2 = (ull*)Ktpf;

    for (int e = tid; e < 48 * (Dn/4); e += ATHREADS) {
        int u = e % 48;
        int c = e / 48;
        float4 qf = make_float4(0.f, 0.f, 0.f, 0.f);
        if (u < NTOP) {
            int lq = g_top[bh*NTOP + u];
            qf = *((const float4*)(q + (((size_t)b*Ln + lq)*Hn + h)*Dn) + c);
        }
        Qt[(4*c+0)*48 + u] = qf.x;
        Qt[(4*c+1)*48 + u] = qf.y;
        Qt[(4*c+2)*48 + u] = qf.z;
        Qt[(4*c+3)*48 + u] = qf.w;
    }

    int base_l = split * SUB;
    for (int e = tid; e < SUB * (Dn/4); e += ATHREADS) {
        int j  = e & 63;
        int c4 = e >> 6;
        size_t g = (((size_t)b*Ln + base_l + j)*Hn + h)*Dn;
        float4 kf = *((const float4*)(k + g) + c4);
        float4 vf = *((const float4*)(v + g) + c4);
        ((float4*)Vs2)[j*16 + c4] = vf;
        int jj = j & 31, hi = j >> 5;
        Ktpf[((4*c4+0)*32 + jj)*2 + hi] = kf.x;
        Ktpf[((4*c4+1)*32 + jj)*2 + hi] = kf.y;
        Ktpf[((4*c4+2)*32 + jj)*2 + hi] = kf.z;
        Ktpf[((4*c4+3)*32 + jj)*2 + hi] = kf.w;
    }
    __syncthreads();

    ull sq0[4] = {0,0,0,0}, sq1[4] = {0,0,0,0};
    #pragma unroll 16
    for (int d = 0; d < Dn; d++) {
        float2 kp = *(const float2*)&Ktpf[(d*32 + lane)*2];
        ull k0 = pk2(kp.x, kp.x);
        ull k1 = pk2(kp.y, kp.y);
        const ull* qd = (const ull*)(Qt + d*48 + 8*warp);
        ull qp0 = qd[0], qp1 = qd[1], qp2 = qd[2], qp3 = qd[3];
        ffma2(sq0[0], qp0, k0);  ffma2(sq1[0], qp0, k1);
        ffma2(sq0[1], qp1, k0);  ffma2(sq1[1], qp1, k1);
        ffma2(sq0[2], qp2, k0);  ffma2(sq1[2], qp2, k1);
        ffma2(sq0[3], qp3, k0);  ffma2(sq1[3], qp3, k1);
    }
    __syncthreads();

    const float scale = 0.125f;
    float lt[8];
    #pragma unroll
    for (int i = 0; i < 8; i++) lt[i] = 0.f;
    ull* pw = ps2 + warp * (SUB*4);
    #pragma unroll
    for (int p = 0; p < 4; p++) {
        float sa, sb, sc, sd;
        upk2(sa, sb, sq0[p]);
        upk2(sc, sd, sq1[p]);
        float pa = __expf(sa * scale);
        float pb = __expf(sb * scale);
        float pc = __expf(sc * scale);
        float pd = __expf(sd * scale);
        pw[lane*4 + p]      = pk2(pa, pb);
        pw[(lane+32)*4 + p] = pk2(pc, pd);
        lt[2*p]   = pa + pc;
        lt[2*p+1] = pb + pd;
    }
    __syncwarp();

    ull accx[4] = {0,0,0,0}, accy[4] = {0,0,0,0};
    #pragma unroll 4
    for (int j = 0; j < SUB; j++) {
        float2 vv = Vs2[j*32 + lane];
        ull vx = pk2(vv.x, vv.x);
        ull vy = pk2(vv.y, vv.y);
        const ull* pj = &pw[j*4];
        ull pp0 = pj[0], pp1 = pj[1], pp2 = pj[2], pp3 = pj[3];
        ffma2(accx[0], pp0, vx);  ffma2(accy[0], pp0, vy);
        ffma2(accx[1], pp1, vx);  ffma2(accy[1], pp1, vy);
        ffma2(accx[2], pp2, vx);  ffma2(accy[2], pp2, vy);
        ffma2(accx[3], pp3, vx);  ffma2(accy[3], pp3, vy);
    }

    #pragma unroll
    for (int i = 0; i < 8; i++) {
        #pragma unroll
        for (int o = 16; o; o >>= 1) lt[i] += __shfl_xor_sync(0xffffffffu, lt[i], o);
    }
    #pragma unroll
    for (int p = 0; p < 4; p++) {
        float ax0, ax1, ay0, ay1;
        upk2(ax0, ax1, accx[p]);
        upk2(ay0, ay1, accy[p]);
        int u0 = 8*warp + 2*p, u1 = u0 + 1;
        if (u0 < NTOP) {
            size_t pidx = (size_t)(bh*NTOP + u0)*SPLITS + split;
            if (lane == 0) g_pl[pidx] = lt[2*p];
            *(float2*)(g_pacc + pidx*Dn + 2*lane) = make_float2(ax0, ay0);
        }
        if (u1 < NTOP) {
            size_t pidx = (size_t)(bh*NTOP + u1)*SPLITS + split;
            if (lane == 0) g_pl[pidx] = lt[2*p+1];
            *(float2*)(g_pacc + pidx*Dn + 2*lane) = make_float2(ax1, ay1);
        }
    }
}

// ---------------- stage 4: combine splits + scatter (per half) ----------------
__global__ __launch_bounds__(256) void k_combine(float* __restrict__ out, int bh0) {
    int gi = (bh0 * NTOP) + blockIdx.x;
    int bh = gi / NTOP, u = gi % NTOP;
    int b = bh / Hn, h = bh % Hn;
    int tid = threadIdx.x;
    int grp = tid >> 6, d = tid & 63;

    __shared__ float lsh[SPLITS];
    __shared__ float part[4][64];

    if (tid < SPLITS) lsh[tid] = g_pl[(size_t)gi*SPLITS + tid];
    __syncthreads();

    float a = 0.f;
    #pragma unroll
    for (int s16 = 0; s16 < SPLITS/4; s16++)
        a += g_pacc[((size_t)gi*SPLITS + grp*(SPLITS/4) + s16)*Dn + d];
    part[grp][d] = a;
    __syncthreads();

    if (grp == 0) {
        float den = 0.f;
        #pragma unroll
        for (int s = 0; s < SPLITS; s++) den += lsh[s];
        float tot = part[0][d] + part[1][d] + part[2][d] + part[3][d];
        int lq = g_top[bh*NTOP + u];
        out[(((size_t)b*Ln + lq)*Hn + h)*Dn + d] = tot / den;
    }
}

// ---------------- launch: both pipelines on explicit non-default streams ----------------
extern "C" void kernel_launch(void* const* d_in, const int* in_sizes, int n_in,
                              void* d_out, int out_size) {
    const float* q = (const float*)d_in[0];
    const float* k = (const float*)d_in[1];
    const float* v = (const float*)d_in[2];
    const unsigned* idxraw = (const unsigned*)d_in[4];
    float* out = (float*)d_out;

    static cudaStream_t sA = nullptr, sB = nullptr;
    static cudaEvent_t evRoot = nullptr, evMS = nullptr, evM = nullptr,
                       evA = nullptr, evB = nullptr;
    if (sA == nullptr) {
        cudaStreamCreateWithFlags(&sA, cudaStreamNonBlocking);
        cudaStreamCreateWithFlags(&sB, cudaStreamNonBlocking);
        cudaEventCreateWithFlags(&evRoot, cudaEventDisableTiming);
        cudaEventCreateWithFlags(&evMS,   cudaEventDisableTiming);
        cudaEventCreateWithFlags(&evM,    cudaEventDisableTiming);
        cudaEventCreateWithFlags(&evA,    cudaEventDisableTiming);
        cudaEventCreateWithFlags(&evB,    cudaEventDisableTiming);
    }

    // fork memset onto sB while origin stream converts + screens
    cudaEventRecord(evRoot, 0);
    cudaStreamWaitEvent(sB, evRoot, 0);
    cudaMemsetAsync(d_out, 0, (size_t)out_size * sizeof(float), sB);
    cudaEventRecord(evMS, sB);

    k_init   <<<(Bn*Ln*Hn*Dn/8)/256, 256>>>(k, idxraw);
    k_scoreM <<<(Bn*Ln)/8, 256>>>(q, idxraw);
    cudaEventRecord(evM, 0);

    // both pipelines on explicit streams (no legacy-stream serialization)
    cudaStreamWaitEvent(sA, evM, 0);
    cudaStreamWaitEvent(sA, evMS, 0);   // combineA writes d_out
    cudaStreamWaitEvent(sB, evM, 0);

    dim3 gAttn(SPLITS, BHn/2);
    k_cand   <<<BHn/2, 1024, 0, sA>>>(0);
    k_cand   <<<BHn/2, 1024, 0, sB>>>(BHn/2);
    k_rescore<<<(BHn/2)*NCAND*2/8, 256, 0, sA>>>(q, k, idxraw, 0);
    k_rescore<<<(BHn/2)*NCAND*2/8, 256, 0, sB>>>(q, k, idxraw, BHn/2);
    k_sel45  <<<BHn/2, NCAND, 0, sA>>>(0);
    k_sel45  <<<BHn/2, NCAND, 0, sB>>>(BHn/2);
    k_attn   <<<gAttn, ATHREADS, 0, sA>>>(q, k, v, 0);
    k_attn   <<<gAttn, ATHREADS, 0, sB>>>(q, k, v, BHn/2);
    k_combine<<<(BHn/2)*NTOP, 256, 0, sA>>>(out, 0);
    k_combine<<<(BHn/2)*NTOP, 256, 0, sB>>>(out, BHn/2);

    // join both streams back to the capture-origin stream
    cudaEventRecord(evA, sA);
    cudaEventRecord(evB, sB);
    cudaStreamWaitEvent(0, evA, 0);
    cudaStreamWaitEvent(0, evB, 0);
}

// round 16
// speedup vs baseline: 1.4911x; 1.4911x over previous
#include <cuda_runtime.h>
#include <cuda_fp16.h>
#include <cuda_fp8.h>
#include <cstdint>
#include <cfloat>
#include <math.h>

#define Bn 2
#define Ln 4096
#define Hn 8
#define Dn 64
#define NTOP 45
#define NSAMP 45
#define NCAND 160
#define BHn (Bn*Hn)
#define SPLITS 64
#define SUB 64
#define AWARPS 6
#define ATHREADS (AWARPS*32)

typedef unsigned long long ull;

__device__ __forceinline__ ull pk2(float x, float y) {
    ull r; asm("mov.b64 %0, {%1, %2};" : "=l"(r) : "f"(x), "f"(y)); return r;
}
__device__ __forceinline__ void upk2(float& x, float& y, ull v) {
    asm("mov.b64 {%0, %1}, %2;" : "=f"(x), "=f"(y) : "l"(v));
}
__device__ __forceinline__ void ffma2(ull& acc, ull a, ull b) {
    asm("fma.rn.f32x2 %0, %1, %2, %3;" : "=l"(acc) : "l"(a), "l"(b), "l"(acc));
}

// ---------------- device scratch ----------------
__device__ float    g_M[BHn * Ln];
__device__ int      g_cand[BHn * NCAND];
__device__ float    g_Mex[BHn * NCAND];
__device__ int      g_top[BHn * NTOP];
__device__ unsigned g_anyodd = 0u;
__device__ unsigned g_Kf8[(size_t)Bn*Ln*Hn*Dn/4];   // e4m3 copy of K, 4 MB
__device__ float    g_Qt[BHn * Dn * 48];             // transposed Q tiles, 196 KB
__device__ float    g_pl [BHn * NTOP * SPLITS];
__device__ float    g_pacc[(size_t)BHn * NTOP * SPLITS * Dn];  // 11.8 MB

// ---------------- K -> fp8 copy + index dtype detect (fused) ----------------
__global__ __launch_bounds__(256) void k_init(const float* __restrict__ k,
                                              const unsigned* __restrict__ raw) {
    int i = blockIdx.x * 256 + threadIdx.x;
    float4 f0 = ((const float4*)k)[2*i];
    float4 f1 = ((const float4*)k)[2*i+1];
    unsigned s0 = __nv_cvt_float2_to_fp8x2(make_float2(f0.x,f0.y), __NV_SATFINITE, __NV_E4M3);
    unsigned s1 = __nv_cvt_float2_to_fp8x2(make_float2(f0.z,f0.w), __NV_SATFINITE, __NV_E4M3);
    unsigned s2 = __nv_cvt_float2_to_fp8x2(make_float2(f1.x,f1.y), __NV_SATFINITE, __NV_E4M3);
    unsigned s3 = __nv_cvt_float2_to_fp8x2(make_float2(f1.z,f1.w), __NV_SATFINITE, __NV_E4M3);
    *(uint2*)&g_Kf8[2*i] = make_uint2(s0 | (s1 << 16), s2 | (s3 << 16));

    if (blockIdx.x < 90) {
        unsigned v = 0;
        for (int j = 1 + 2*i; j < Ln*NSAMP; j += 2*90*256) v |= raw[j];
        #pragma unroll
        for (int o = 16; o; o >>= 1) v |= __shfl_xor_sync(0xffffffffu, v, o);
        if ((threadIdx.x & 31) == 0 && v) atomicOr(&g_anyodd, v);
    }
}

// ---------------- stage 1: fp8 screen, one warp = (b,l) x all 8 heads ----------------
__global__ __launch_bounds__(256) void k_scoreM(const float* __restrict__ q,
                                                const unsigned* __restrict__ raw) {
    int w    = (blockIdx.x * 256 + threadIdx.x) >> 5;
    int lane = threadIdx.x & 31;
    int head = lane >> 2;
    int quad = lane & 3;
    int b = w / Ln, l = w % Ln;

    const float4* qp = (const float4*)(q + (((size_t)b*Ln + l)*Hn + head)*Dn + quad*16);
    half2 qh[8];
    #pragma unroll
    for (int j = 0; j < 4; j++) {
        float4 f = qp[j];
        qh[2*j]   = __floats2half2_rn(f.x, f.y);
        qh[2*j+1] = __floats2half2_rn(f.z, f.w);
    }

    int sh = (g_anyodd == 0u) ? 1 : 0;
    const unsigned* ip = raw + ((size_t)(l * NSAMP) << sh);
    int i0 = (int)ip[(unsigned)lane << sh];
    int i1 = (lane < NSAMP - 32) ? (int)ip[(unsigned)(32 + lane) << sh] : 0;

    const uint4* kb = (const uint4*)g_Kf8 + (size_t)b * (Ln * 32);

    float mx = -FLT_MAX, sm = 0.f;
    #pragma unroll 9
    for (int s = 0; s < NSAMP; s++) {
        int id = __shfl_sync(0xffffffffu, (s < 32) ? i0 : i1, s & 31);
        uint4 kw = __ldg(kb + (id << 5) + lane);
        half2 acc;
        {
            __half2_raw h;
            h = __nv_cvt_fp8x2_to_halfraw2((__nv_fp8x2_storage_t)(kw.x & 0xffff), __NV_E4M3);
            acc = __hmul2(*(half2*)&h, qh[0]);
            h = __nv_cvt_fp8x2_to_halfraw2((__nv_fp8x2_storage_t)(kw.x >> 16), __NV_E4M3);
            acc = __hfma2(*(half2*)&h, qh[1], acc);
            h = __nv_cvt_fp8x2_to_halfraw2((__nv_fp8x2_storage_t)(kw.y & 0xffff), __NV_E4M3);
            acc = __hfma2(*(half2*)&h, qh[2], acc);
            h = __nv_cvt_fp8x2_to_halfraw2((__nv_fp8x2_storage_t)(kw.y >> 16), __NV_E4M3);
            acc = __hfma2(*(half2*)&h, qh[3], acc);
            h = __nv_cvt_fp8x2_to_halfraw2((__nv_fp8x2_storage_t)(kw.z & 0xffff), __NV_E4M3);
            acc = __hfma2(*(half2*)&h, qh[4], acc);
            h = __nv_cvt_fp8x2_to_halfraw2((__nv_fp8x2_storage_t)(kw.z >> 16), __NV_E4M3);
            acc = __hfma2(*(half2*)&h, qh[5], acc);
            h = __nv_cvt_fp8x2_to_halfraw2((__nv_fp8x2_storage_t)(kw.w & 0xffff), __NV_E4M3);
            acc = __hfma2(*(half2*)&h, qh[6], acc);
            h = __nv_cvt_fp8x2_to_halfraw2((__nv_fp8x2_storage_t)(kw.w >> 16), __NV_E4M3);
            acc = __hfma2(*(half2*)&h, qh[7], acc);
        }
        float d = __low2float(acc) + __high2float(acc);
        d += __shfl_xor_sync(0xffffffffu, d, 1);
        d += __shfl_xor_sync(0xffffffffu, d, 2);
        mx = fmaxf(mx, d);
        sm += d;
    }
    if (quad == 0)
        g_M[(b*Hn + head)*Ln + l] = mx - sm * (1.0f / (float)Ln);
}

// ---------------- stage 2a: top-160 candidates via radix-256 select ----------------
__global__ __launch_bounds__(1024) void k_cand(int bh0) {
    int bh  = bh0 + blockIdx.x;
    int tid = threadIdx.x;
    int lane = tid & 31;

    __shared__ int bins[256];
    __shared__ int ssum[256];
    __shared__ int s_sel, s_need, s_out;

    unsigned r[4];
    #pragma unroll
    for (int i = 0; i < 4; i++) {
        unsigned u = __float_as_uint(g_M[bh*Ln + tid + i*1024]);
        r[i] = (u & 0x80000000u) ? ~u : (u | 0x80000000u);
    }

    unsigned prefix = 0;
    int need = NCAND;
    #pragma unroll
    for (int p = 0; p < 4; p++) {
        int shift = 24 - 8*p;
        unsigned pmask = (p == 0) ? 0u : (0xFFFFFFFFu << (32 - 8*p));
        if (tid < 256) bins[tid] = 0;
        __syncthreads();
        #pragma unroll
        for (int i = 0; i < 4; i++)
            if ((r[i] & pmask) == prefix)
                atomicAdd(&bins[(r[i] >> shift) & 255], 1);
        __syncthreads();
        if (tid < 32) {
            int x[8], loc = 0;
            #pragma unroll
            for (int j = 0; j < 8; j++) { x[j] = bins[lane*8 + j]; loc += x[j]; }
            int suf = loc;
            #pragma unroll
            for (int o = 1; o < 32; o <<= 1) {
                int t = __shfl_down_sync(0xffffffffu, suf, o);
                if (lane + o < 32) suf += t;
            }
            int run = suf - loc;
            #pragma unroll
            for (int j = 7; j >= 0; j--) { run += x[j]; ssum[lane*8 + j] = run; }
        }
        __syncthreads();
        if (tid < 256) {
            int above = (tid < 255) ? ssum[tid + 1] : 0;
            if (ssum[tid] >= need && above < need) { s_sel = tid; s_need = need - above; }
        }
        __syncthreads();
        prefix |= ((unsigned)s_sel) << shift;
        need    = s_need;
        __syncthreads();
    }
    unsigned T = prefix;

    if (tid == 0) s_out = 0;
    __syncthreads();
    #pragma unroll
    for (int i = 0; i < 4; i++)
        if (r[i] > T) {
            int p = atomicAdd(&s_out, 1);
            g_cand[bh*NCAND + p] = tid + i*1024;
        }
    __syncthreads();
    #pragma unroll
    for (int i = 0; i < 4; i++)
        if (r[i] == T) {
            int p = atomicAdd(&s_out, 1);
            if (p < NCAND) g_cand[bh*NCAND + p] = tid + i*1024;
        }
}

// ---------------- stage 2b: exact fp32 rescore, 2 warps per candidate ----------------
__global__ __launch_bounds__(256) void k_rescore(const float* __restrict__ q,
                                                 const float* __restrict__ k,
                                                 const unsigned* __restrict__ raw,
                                                 int bh0) {
    int wp   = (blockIdx.x * 256 + threadIdx.x) >> 5;
    int lane = threadIdx.x & 31;
    int c2   = wp >> 1;
    int half = wp & 1;
    int grp  = lane >> 4;
    int sub  = lane & 15;
    int bh = bh0 + c2 / NCAND;
    int c  = c2 % NCAND;
    int b = bh / Hn, h = bh % Hn;
    int l = g_cand[bh*NCAND + c];

    const float4 qv = *((const float4*)(q + (((size_t)b*Ln + l)*Hn + h)*Dn) + sub);

    int sh = (g_anyodd == 0u) ? 1 : 0;
    const unsigned* ip = raw + ((size_t)(l * NSAMP) << sh);
    int base_s = half * 23;
    int ii = (lane < 23 && base_s + lane < NSAMP)
           ? (int)ip[(unsigned)(base_s + lane) << sh] : 0;

    const float4* kbase = (const float4*)(k + ((size_t)b*Ln*Hn + h)*Dn);

    float mx = -FLT_MAX, sm = 0.f;
    #pragma unroll
    for (int t = 0; t < 12; t++) {
        int sl = 2*t + grp;
        int id = __shfl_sync(0xffffffffu, ii, sl & 31);
        float4 kv = __ldg(kbase + (size_t)id*(Hn*Dn/4) + sub);
        float d = qv.x*kv.x + qv.y*kv.y + qv.z*kv.z + qv.w*kv.w;
        #pragma unroll
        for (int o = 1; o < 16; o <<= 1) d += __shfl_xor_sync(0xffffffffu, d, o);
        if (sl < 23 && base_s + sl < NSAMP) { mx = fmaxf(mx, d); sm += d; }
    }
    mx = fmaxf(mx, __shfl_xor_sync(0xffffffffu, mx, 16));
    sm += __shfl_xor_sync(0xffffffffu, sm, 16);

    __shared__ float2 s_part[8];
    int wloc = threadIdx.x >> 5;
    if (lane == 0) s_part[wloc] = make_float2(mx, sm);
    __syncthreads();
    if (half == 0 && lane == 0) {
        float2 o = s_part[wloc ^ 1];
        mx = fmaxf(mx, o.x);
        sm += o.y;
        g_Mex[bh*NCAND + c] = mx - sm * (1.0f / (float)Ln);
    }
}

// ---------------- stage 2c: exact top-45 of 160 (jax tie-break) ----------------
__global__ __launch_bounds__(NCAND) void k_sel45(int bh0) {
    int bh  = bh0 + blockIdx.x;
    int tid = threadIdx.x;
    __shared__ unsigned long long comp[NCAND];

    int idx = g_cand[bh*NCAND + tid];
    unsigned u = __float_as_uint(g_Mex[bh*NCAND + tid]);
    u = (u & 0x80000000u) ? ~u : (u | 0x80000000u);
    comp[tid] = ((unsigned long long)u << 32) | (unsigned)(Ln - 1 - idx);
    __syncthreads();

    unsigned long long mine = comp[tid];
    int rank = 0;
    #pragma unroll 16
    for (int j = 0; j < NCAND; j++) rank += (comp[j] > mine);
    if (rank < NTOP) g_top[bh*NTOP + rank] = idx;
}

// ---------------- stage 2d: stage transposed Q tiles once per bh ----------------
__global__ __launch_bounds__(256) void k_qstage(const float* __restrict__ q, int bh0) {
    int bh = bh0 + blockIdx.x;
    int b = bh / Hn, h = bh % Hn;
    int tid = threadIdx.x;
    float* dst = g_Qt + (size_t)bh * Dn * 48;
    for (int e = tid; e < 48 * (Dn/4); e += 256) {
        int u = e % 48;
        int c = e / 48;
        float4 qf = make_float4(0.f, 0.f, 0.f, 0.f);
        if (u < NTOP) {
            int lq = g_top[bh*NTOP + u];
            qf = *((const float4*)(q + (((size_t)b*Ln + lq)*Hn + h)*Dn) + c);
        }
        dst[(4*c+0)*48 + u] = qf.x;
        dst[(4*c+1)*48 + u] = qf.y;
        dst[(4*c+2)*48 + u] = qf.z;
        dst[(4*c+3)*48 + u] = qf.w;
    }
}

// ---------------- stage 3: split-KV attention, Q from L1-resident global ----------------
__global__ __launch_bounds__(ATHREADS, 5) void k_attn(const float* __restrict__ k,
                                                      const float* __restrict__ v,
                                                      int bh0) {
    int split = blockIdx.x;
    int bh    = bh0 + blockIdx.y;
    int b = bh / Hn, h = bh % Hn;
    int tid = threadIdx.x, warp = tid >> 5, lane = tid & 31;

    __shared__ __align__(16) float Ktpf[Dn * SUB];    // 16 KB; aliased as ps2 later
    __shared__ __align__(16) float2 Vs2[SUB * 32];    // 16 KB
    ull* ps2 = (ull*)Ktpf;

    int base_l = split * SUB;
    for (int e = tid; e < SUB * (Dn/4); e += ATHREADS) {
        int j  = e & 63;
        int c4 = e >> 6;
        size_t g = (((size_t)b*Ln + base_l + j)*Hn + h)*Dn;
        float4 kf = *((const float4*)(k + g) + c4);
        float4 vf = *((const float4*)(v + g) + c4);
        ((float4*)Vs2)[j*16 + c4] = vf;
        int jj = j & 31, hi = j >> 5;
        Ktpf[((4*c4+0)*32 + jj)*2 + hi] = kf.x;
        Ktpf[((4*c4+1)*32 + jj)*2 + hi] = kf.y;
        Ktpf[((4*c4+2)*32 + jj)*2 + hi] = kf.z;
        Ktpf[((4*c4+3)*32 + jj)*2 + hi] = kf.w;
    }
    __syncthreads();

    const ull* qtile = (const ull*)(g_Qt + (size_t)bh * Dn * 48) + 4*warp;  // row d: +d*24

    ull sq0[4] = {0,0,0,0}, sq1[4] = {0,0,0,0};
    #pragma unroll 16
    for (int d = 0; d < Dn; d++) {
        float2 kp = *(const float2*)&Ktpf[(d*32 + lane)*2];
        ull k0 = pk2(kp.x, kp.x);
        ull k1 = pk2(kp.y, kp.y);
        const ull* qd = qtile + d*24;
        ull qp0 = __ldg(qd+0), qp1 = __ldg(qd+1), qp2 = __ldg(qd+2), qp3 = __ldg(qd+3);
        ffma2(sq0[0], qp0, k0);  ffma2(sq1[0], qp0, k1);
        ffma2(sq0[1], qp1, k0);  ffma2(sq1[1], qp1, k1);
        ffma2(sq0[2], qp2, k0);  ffma2(sq1[2], qp2, k1);
        ffma2(sq0[3], qp3, k0);  ffma2(sq1[3], qp3, k1);
    }
    __syncthreads();                   // Ktpf consumed; alias as ps2

    const float scale = 0.125f;
    float lt[8];
    #pragma unroll
    for (int i = 0; i < 8; i++) lt[i] = 0.f;
    ull* pw = ps2 + warp * (SUB*4);
    #pragma unroll
    for (int p = 0; p < 4; p++) {
        float sa, sb, sc, sd;
        upk2(sa, sb, sq0[p]);
        upk2(sc, sd, sq1[p]);
        float pa = __expf(sa * scale);
        float pb = __expf(sb * scale);
        float pc = __expf(sc * scale);
        float pd = __expf(sd * scale);
        pw[lane*4 + p]      = pk2(pa, pb);
        pw[(lane+32)*4 + p] = pk2(pc, pd);
        lt[2*p]   = pa + pc;
        lt[2*p+1] = pb + pd;
    }
    __syncwarp();

    ull accx[4] = {0,0,0,0}, accy[4] = {0,0,0,0};
    #pragma unroll 4
    for (int j = 0; j < SUB; j++) {
        float2 vv = Vs2[j*32 + lane];
        ull vx = pk2(vv.x, vv.x);
        ull vy = pk2(vv.y, vv.y);
        const ull* pj = &pw[j*4];
        ull pp0 = pj[0], pp1 = pj[1], pp2 = pj[2], pp3 = pj[3];
        ffma2(accx[0], pp0, vx);  ffma2(accy[0], pp0, vy);
        ffma2(accx[1], pp1, vx);  ffma2(accy[1], pp1, vy);
        ffma2(accx[2], pp2, vx);  ffma2(accy[2], pp2, vy);
        ffma2(accx[3], pp3, vx);  ffma2(accy[3], pp3, vy);
    }

    #pragma unroll
    for (int i = 0; i < 8; i++) {
        #pragma unroll
        for (int o = 16; o; o >>= 1) lt[i] += __shfl_xor_sync(0xffffffffu, lt[i], o);
    }
    #pragma unroll
    for (int p = 0; p < 4; p++) {
        float ax0, ax1, ay0, ay1;
        upk2(ax0, ax1, accx[p]);
        upk2(ay0, ay1, accy[p]);
        int u0 = 8*warp + 2*p, u1 = u0 + 1;
        if (u0 < NTOP) {
            size_t pidx = (size_t)(bh*NTOP + u0)*SPLITS + split;
            if (lane == 0) g_pl[pidx] = lt[2*p];
            *(float2*)(g_pacc + pidx*Dn + 2*lane) = make_float2(ax0, ay0);
        }
        if (u1 < NTOP) {
            size_t pidx = (size_t)(bh*NTOP + u1)*SPLITS + split;
            if (lane == 0) g_pl[pidx] = lt[2*p+1];
            *(float2*)(g_pacc + pidx*Dn + 2*lane) = make_float2(ax1, ay1);
        }
    }
}

// ---------------- stage 4: combine splits + scatter ----------------
__global__ __launch_bounds__(256) void k_combine(float* __restrict__ out) {
    int gi = blockIdx.x;
    int bh = gi / NTOP, u = gi % NTOP;
    int b = bh / Hn, h = bh % Hn;
    int tid = threadIdx.x;
    int grp = tid >> 6, d = tid & 63;

    __shared__ float lsh[SPLITS];
    __shared__ float part[4][64];

    if (tid < SPLITS) lsh[tid] = g_pl[(size_t)gi*SPLITS + tid];
    __syncthreads();

    float a = 0.f;
    #pragma unroll
    for (int s16 = 0; s16 < SPLITS/4; s16++)
        a += g_pacc[((size_t)gi*SPLITS + grp*(SPLITS/4) + s16)*Dn + d];
    part[grp][d] = a;
    __syncthreads();

    if (grp == 0) {
        float den = 0.f;
        #pragma unroll
        for (int s = 0; s < SPLITS; s++) den += lsh[s];
        float tot = part[0][d] + part[1][d] + part[2][d] + part[3][d];
        int lq = g_top[bh*NTOP + u];
        out[(((size_t)b*Ln + lq)*Hn + h)*Dn + d] = tot / den;
    }
}

// ---------------- launch: R14 topology (A on origin stream, B + memset on sB) ----------------
extern "C" void kernel_launch(void* const* d_in, const int* in_sizes, int n_in,
                              void* d_out, int out_size) {
    const float* q = (const float*)d_in[0];
    const float* k = (const float*)d_in[1];
    const float* v = (const float*)d_in[2];
    const unsigned* idxraw = (const unsigned*)d_in[4];
    float* out = (float*)d_out;

    static cudaStream_t sB = nullptr;
    static cudaEvent_t evRoot = nullptr, evM = nullptr, evB = nullptr;
    if (sB == nullptr) {
        cudaStreamCreateWithFlags(&sB, cudaStreamNonBlocking);
        cudaEventCreateWithFlags(&evRoot, cudaEventDisableTiming);
        cudaEventCreateWithFlags(&evM,    cudaEventDisableTiming);
        cudaEventCreateWithFlags(&evB,    cudaEventDisableTiming);
    }

    // fork: sB does the big output memset while main stream converts + screens
    cudaEventRecord(evRoot, 0);
    cudaStreamWaitEvent(sB, evRoot, 0);
    cudaMemsetAsync(d_out, 0, (size_t)out_size * sizeof(float), sB);

    k_init   <<<(Bn*Ln*Hn*Dn/8)/256, 256>>>(k, idxraw);
    k_scoreM <<<(Bn*Ln)/8, 256>>>(q, idxraw);
    cudaEventRecord(evM, 0);
    cudaStreamWaitEvent(sB, evM, 0);

    // pipeline A (main stream): bh 0..7 ; pipeline B (sB): bh 8..15
    dim3 gAttn(SPLITS, BHn/2);
    k_cand   <<<BHn/2, 1024>>>(0);
    k_cand   <<<BHn/2, 1024, 0, sB>>>(BHn/2);
    k_rescore<<<(BHn/2)*NCAND*2/8, 256>>>(q, k, idxraw, 0);
    k_rescore<<<(BHn/2)*NCAND*2/8, 256, 0, sB>>>(q, k, idxraw, BHn/2);
    k_sel45  <<<BHn/2, NCAND>>>(0);
    k_sel45  <<<BHn/2, NCAND, 0, sB>>>(BHn/2);
    k_qstage <<<BHn/2, 256>>>(q, 0);
    k_qstage <<<BHn/2, 256, 0, sB>>>(q, BHn/2);
    k_attn   <<<gAttn, ATHREADS>>>(k, v, 0);
    k_attn   <<<gAttn, ATHREADS, 0, sB>>>(k, v, BHn/2);

    // join: combine needs both attns and the memset
    cudaEventRecord(evB, sB);
    cudaStreamWaitEvent(0, evB, 0);
    k_combine<<<BHn*NTOP, 256>>>(out);
}

// round 17
// speedup vs baseline: 1.5313x; 1.0270x over previous
#include <cuda_runtime.h>
#include <cuda_fp16.h>
#include <cuda_fp8.h>
#include <cstdint>
#include <cfloat>
#include <math.h>

#define Bn 2
#define Ln 4096
#define Hn 8
#define Dn 64
#define NTOP 45
#define NSAMP 45
#define NCAND 160
#define BHn (Bn*Hn)
#define SPLITS 64
#define SUB 64
#define AWARPS 6
#define ATHREADS (AWARPS*32)

typedef unsigned long long ull;

__device__ __forceinline__ ull pk2(float x, float y) {
    ull r; asm("mov.b64 %0, {%1, %2};" : "=l"(r) : "f"(x), "f"(y)); return r;
}
__device__ __forceinline__ void upk2(float& x, float& y, ull v) {
    asm("mov.b64 {%0, %1}, %2;" : "=f"(x), "=f"(y) : "l"(v));
}
__device__ __forceinline__ void ffma2(ull& acc, ull a, ull b) {
    asm("fma.rn.f32x2 %0, %1, %2, %3;" : "=l"(acc) : "l"(a), "l"(b), "l"(acc));
}

// ---------------- device scratch ----------------
__device__ float    g_M[BHn * Ln];
__device__ int      g_cand[BHn * NCAND];
__device__ float    g_Mex[BHn * NCAND];
__device__ int      g_top[BHn * NTOP];
__device__ unsigned g_anyodd = 0u;
__device__ unsigned g_Kf8[(size_t)Bn*Ln*Hn*Dn/4];   // e4m3 copy of K, 4 MB
__device__ float    g_pl [BHn * NTOP * SPLITS];
__device__ float    g_pacc[(size_t)BHn * NTOP * SPLITS * Dn];  // 11.8 MB

// ---------------- K -> fp8 copy + index dtype detect (fused) ----------------
__global__ __launch_bounds__(256) void k_init(const float* __restrict__ k,
                                              const unsigned* __restrict__ raw) {
    int i = blockIdx.x * 256 + threadIdx.x;
    float4 f0 = ((const float4*)k)[2*i];
    float4 f1 = ((const float4*)k)[2*i+1];
    unsigned s0 = __nv_cvt_float2_to_fp8x2(make_float2(f0.x,f0.y), __NV_SATFINITE, __NV_E4M3);
    unsigned s1 = __nv_cvt_float2_to_fp8x2(make_float2(f0.z,f0.w), __NV_SATFINITE, __NV_E4M3);
    unsigned s2 = __nv_cvt_float2_to_fp8x2(make_float2(f1.x,f1.y), __NV_SATFINITE, __NV_E4M3);
    unsigned s3 = __nv_cvt_float2_to_fp8x2(make_float2(f1.z,f1.w), __NV_SATFINITE, __NV_E4M3);
    *(uint2*)&g_Kf8[2*i] = make_uint2(s0 | (s1 << 16), s2 | (s3 << 16));

    if (blockIdx.x < 90) {
        unsigned v = 0;
        for (int j = 1 + 2*i; j < Ln*NSAMP; j += 2*90*256) v |= raw[j];
        #pragma unroll
        for (int o = 16; o; o >>= 1) v |= __shfl_xor_sync(0xffffffffu, v, o);
        if ((threadIdx.x & 31) == 0 && v) atomicOr(&g_anyodd, v);
    }
}

// ---------------- stage 1: fp8 screen, one warp = (b,l) x all 8 heads ----------------
__global__ __launch_bounds__(256) void k_scoreM(const float* __restrict__ q,
                                                const unsigned* __restrict__ raw) {
    int w    = (blockIdx.x * 256 + threadIdx.x) >> 5;
    int lane = threadIdx.x & 31;
    int head = lane >> 2;
    int quad = lane & 3;
    int b = w / Ln, l = w % Ln;

    const float4* qp = (const float4*)(q + (((size_t)b*Ln + l)*Hn + head)*Dn + quad*16);
    half2 qh[8];
    #pragma unroll
    for (int j = 0; j < 4; j++) {
        float4 f = qp[j];
        qh[2*j]   = __floats2half2_rn(f.x, f.y);
        qh[2*j+1] = __floats2half2_rn(f.z, f.w);
    }

    int sh = (g_anyodd == 0u) ? 1 : 0;
    const unsigned* ip = raw + ((size_t)(l * NSAMP) << sh);
    int i0 = (int)ip[(unsigned)lane << sh];
    int i1 = (lane < NSAMP - 32) ? (int)ip[(unsigned)(32 + lane) << sh] : 0;

    const uint4* kb = (const uint4*)g_Kf8 + (size_t)b * (Ln * 32);

    float mx = -FLT_MAX, sm = 0.f;
    #pragma unroll 9
    for (int s = 0; s < NSAMP; s++) {
        int id = __shfl_sync(0xffffffffu, (s < 32) ? i0 : i1, s & 31);
        uint4 kw = __ldg(kb + (id << 5) + lane);
        half2 acc;
        {
            __half2_raw h;
            h = __nv_cvt_fp8x2_to_halfraw2((__nv_fp8x2_storage_t)(kw.x & 0xffff), __NV_E4M3);
            acc = __hmul2(*(half2*)&h, qh[0]);
            h = __nv_cvt_fp8x2_to_halfraw2((__nv_fp8x2_storage_t)(kw.x >> 16), __NV_E4M3);
            acc = __hfma2(*(half2*)&h, qh[1], acc);
            h = __nv_cvt_fp8x2_to_halfraw2((__nv_fp8x2_storage_t)(kw.y & 0xffff), __NV_E4M3);
            acc = __hfma2(*(half2*)&h, qh[2], acc);
            h = __nv_cvt_fp8x2_to_halfraw2((__nv_fp8x2_storage_t)(kw.y >> 16), __NV_E4M3);
            acc = __hfma2(*(half2*)&h, qh[3], acc);
            h = __nv_cvt_fp8x2_to_halfraw2((__nv_fp8x2_storage_t)(kw.z & 0xffff), __NV_E4M3);
            acc = __hfma2(*(half2*)&h, qh[4], acc);
            h = __nv_cvt_fp8x2_to_halfraw2((__nv_fp8x2_storage_t)(kw.z >> 16), __NV_E4M3);
            acc = __hfma2(*(half2*)&h, qh[5], acc);
            h = __nv_cvt_fp8x2_to_halfraw2((__nv_fp8x2_storage_t)(kw.w & 0xffff), __NV_E4M3);
            acc = __hfma2(*(half2*)&h, qh[6], acc);
            h = __nv_cvt_fp8x2_to_halfraw2((__nv_fp8x2_storage_t)(kw.w >> 16), __NV_E4M3);
            acc = __hfma2(*(half2*)&h, qh[7], acc);
        }
        float d = __low2float(acc) + __high2float(acc);
        d += __shfl_xor_sync(0xffffffffu, d, 1);
        d += __shfl_xor_sync(0xffffffffu, d, 2);
        mx = fmaxf(mx, d);
        sm += d;
    }
    if (quad == 0)
        g_M[(b*Hn + head)*Ln + l] = mx - sm * (1.0f / (float)Ln);
}

// ---------------- stage 2a: top-160 candidates via 2-pass radix-1024 ----------------
__global__ __launch_bounds__(1024) void k_cand(int bh0) {
    int bh  = bh0 + blockIdx.x;
    int tid = threadIdx.x;
    int lane = tid & 31, warp = tid >> 5;

    __shared__ int bins[1024];
    __shared__ int wsum[32];
    __shared__ int s_sel, s_need, s_out;

    unsigned r[4];
    #pragma unroll
    for (int i = 0; i < 4; i++) {
        unsigned u = __float_as_uint(g_M[bh*Ln + tid + i*1024]);
        r[i] = (u & 0x80000000u) ? ~u : (u | 0x80000000u);
    }

    unsigned prefix = 0;   // resolved top bits (low bits zero)
    int need = NCAND;
    #pragma unroll
    for (int p = 0; p < 2; p++) {
        int shift = (p == 0) ? 22 : 12;
        bins[tid] = 0;
        __syncthreads();
        if (p == 0) {
            #pragma unroll
            for (int i = 0; i < 4; i++)
                atomicAdd(&bins[r[i] >> 22], 1);
        } else {
            #pragma unroll
            for (int i = 0; i < 4; i++)
                if ((r[i] >> 22) == (prefix >> 22))
                    atomicAdd(&bins[(r[i] >> 12) & 1023], 1);
        }
        __syncthreads();
        // two-level suffix scan over 1024 bins
        int v = bins[tid];
        #pragma unroll
        for (int o = 1; o < 32; o <<= 1) {
            int t = __shfl_down_sync(0xffffffffu, v, o);
            if (lane + o < 32) v += t;
        }
        if (lane == 0) wsum[warp] = v;           // total of this warp's 32 bins
        // redistribute: lane L needs suffix within warp = done in v
        __syncthreads();
        if (tid < 32) {
            int wv = wsum[tid];
            #pragma unroll
            for (int o = 1; o < 32; o <<= 1) {
                int t = __shfl_down_sync(0xffffffffu, wv, o);
                if (tid + o < 32) wv += t;
            }
            // exclusive suffix of warps after tid
            int excl = wv - wsum[tid];
            wsum[tid] = excl;
        }
        __syncthreads();
        int ssum_t = v + wsum[warp];             // inclusive suffix from bin tid
        bins[tid] = ssum_t;                      // reuse bins[] as ssum
        __syncthreads();
        {
            int above = (tid < 1023) ? bins[tid + 1] : 0;
            if (ssum_t >= need && above < need) { s_sel = tid; s_need = need - above; }
        }
        __syncthreads();
        prefix |= ((unsigned)s_sel) << shift;
        need    = s_need;
        __syncthreads();
    }
    unsigned Thi = prefix >> 12;   // resolved 20 bits

    if (tid == 0) s_out = 0;
    __syncthreads();
    #pragma unroll
    for (int i = 0; i < 4; i++)
        if ((r[i] >> 12) > Thi) {
            int p = atomicAdd(&s_out, 1);
            g_cand[bh*NCAND + p] = tid + i*1024;
        }
    __syncthreads();
    #pragma unroll
    for (int i = 0; i < 4; i++)
        if ((r[i] >> 12) == Thi) {
            int p = atomicAdd(&s_out, 1);
            if (p < NCAND) g_cand[bh*NCAND + p] = tid + i*1024;
        }
}

// ---------------- stage 2b: exact fp32 rescore, 2 warps per candidate ----------------
__global__ __launch_bounds__(256) void k_rescore(const float* __restrict__ q,
                                                 const float* __restrict__ k,
                                                 const unsigned* __restrict__ raw,
                                                 int bh0) {
    int wp   = (blockIdx.x * 256 + threadIdx.x) >> 5;
    int lane = threadIdx.x & 31;
    int c2   = wp >> 1;
    int half = wp & 1;
    int grp  = lane >> 4;
    int sub  = lane & 15;
    int bh = bh0 + c2 / NCAND;
    int c  = c2 % NCAND;
    int b = bh / Hn, h = bh % Hn;
    int l = g_cand[bh*NCAND + c];

    const float4 qv = *((const float4*)(q + (((size_t)b*Ln + l)*Hn + h)*Dn) + sub);

    int sh = (g_anyodd == 0u) ? 1 : 0;
    const unsigned* ip = raw + ((size_t)(l * NSAMP) << sh);
    int base_s = half * 23;
    int ii = (lane < 23 && base_s + lane < NSAMP)
           ? (int)ip[(unsigned)(base_s + lane) << sh] : 0;

    const float4* kbase = (const float4*)(k + ((size_t)b*Ln*Hn + h)*Dn);

    float mx = -FLT_MAX, sm = 0.f;
    #pragma unroll
    for (int t = 0; t < 12; t++) {
        int sl = 2*t + grp;
        int id = __shfl_sync(0xffffffffu, ii, sl & 31);
        float4 kv = __ldg(kbase + (size_t)id*(Hn*Dn/4) + sub);
        float d = qv.x*kv.x + qv.y*kv.y + qv.z*kv.z + qv.w*kv.w;
        #pragma unroll
        for (int o = 1; o < 16; o <<= 1) d += __shfl_xor_sync(0xffffffffu, d, o);
        if (sl < 23 && base_s + sl < NSAMP) { mx = fmaxf(mx, d); sm += d; }
    }
    mx = fmaxf(mx, __shfl_xor_sync(0xffffffffu, mx, 16));
    sm += __shfl_xor_sync(0xffffffffu, sm, 16);

    __shared__ float2 s_part[8];
    int wloc = threadIdx.x >> 5;
    if (lane == 0) s_part[wloc] = make_float2(mx, sm);
    __syncthreads();
    if (half == 0 && lane == 0) {
        float2 o = s_part[wloc ^ 1];
        mx = fmaxf(mx, o.x);
        sm += o.y;
        g_Mex[bh*NCAND + c] = mx - sm * (1.0f / (float)Ln);
    }
}

// ---------------- stage 2c: exact top-45 of 160 (jax tie-break) ----------------
__global__ __launch_bounds__(NCAND) void k_sel45(int bh0) {
    int bh  = bh0 + blockIdx.x;
    int tid = threadIdx.x;
    __shared__ unsigned long long comp[NCAND];

    int idx = g_cand[bh*NCAND + tid];
    unsigned u = __float_as_uint(g_Mex[bh*NCAND + tid]);
    u = (u & 0x80000000u) ? ~u : (u | 0x80000000u);
    comp[tid] = ((unsigned long long)u << 32) | (unsigned)(Ln - 1 - idx);
    __syncthreads();

    unsigned long long mine = comp[tid];
    int rank = 0;
    #pragma unroll 16
    for (int j = 0; j < NCAND; j++) rank += (comp[j] > mine);
    if (rank < NTOP) g_top[bh*NTOP + rank] = idx;
}

// ---------------- stage 3: split-KV attention, 64 keys/block, FFMA2 ----------------
__global__ __launch_bounds__(ATHREADS, 5) void k_attn(const float* __restrict__ q,
                                                      const float* __restrict__ k,
                                                      const float* __restrict__ v,
                                                      int bh0) {
    int split = blockIdx.x;
    int bh    = bh0 + blockIdx.y;
    int b = bh / Hn, h = bh % Hn;
    int tid = threadIdx.x, warp = tid >> 5, lane = tid & 31;

    __shared__ __align__(16) float Ktpf[Dn * SUB];
    __shared__ __align__(16) float2 Vs2[SUB * 32];
    __shared__ __align__(16) float  Qt[Dn * 48];
    ull* ps2 = (ull*)Ktpf;

    for (int e = tid; e < 48 * (Dn/4); e += ATHREADS) {
        int u = e % 48;
        int c = e / 48;
        float4 qf = make_float4(0.f, 0.f, 0.f, 0.f);
        if (u < NTOP) {
            int lq = g_top[bh*NTOP + u];
            qf = *((const float4*)(q + (((size_t)b*Ln + lq)*Hn + h)*Dn) + c);
        }
        Qt[(4*c+0)*48 + u] = qf.x;
        Qt[(4*c+1)*48 + u] = qf.y;
        Qt[(4*c+2)*48 + u] = qf.z;
        Qt[(4*c+3)*48 + u] = qf.w;
    }

    int base_l = split * SUB;
    for (int e = tid; e < SUB * (Dn/4); e += ATHREADS) {
        int j  = e & 63;
        int c4 = e >> 6;
        size_t g = (((size_t)b*Ln + base_l + j)*Hn + h)*Dn;
        float4 kf = *((const float4*)(k + g) + c4);
        float4 vf = *((const float4*)(v + g) + c4);
        ((float4*)Vs2)[j*16 + c4] = vf;
        int jj = j & 31, hi = j >> 5;
        Ktpf[((4*c4+0)*32 + jj)*2 + hi] = kf.x;
        Ktpf[((4*c4+1)*32 + jj)*2 + hi] = kf.y;
        Ktpf[((4*c4+2)*32 + jj)*2 + hi] = kf.z;
        Ktpf[((4*c4+3)*32 + jj)*2 + hi] = kf.w;
    }
    __syncthreads();

    ull sq0[4] = {0,0,0,0}, sq1[4] = {0,0,0,0};
    #pragma unroll 16
    for (int d = 0; d < Dn; d++) {
        float2 kp = *(const float2*)&Ktpf[(d*32 + lane)*2];
        ull k0 = pk2(kp.x, kp.x);
        ull k1 = pk2(kp.y, kp.y);
        const ull* qd = (const ull*)(Qt + d*48 + 8*warp);
        ull qp0 = qd[0], qp1 = qd[1], qp2 = qd[2], qp3 = qd[3];
        ffma2(sq0[0], qp0, k0);  ffma2(sq1[0], qp0, k1);
        ffma2(sq0[1], qp1, k0);  ffma2(sq1[1], qp1, k1);
        ffma2(sq0[2], qp2, k0);  ffma2(sq1[2], qp2, k1);
        ffma2(sq0[3], qp3, k0);  ffma2(sq1[3], qp3, k1);
    }
    __syncthreads();

    const float scale = 0.125f;
    float lt[8];
    #pragma unroll
    for (int i = 0; i < 8; i++) lt[i] = 0.f;
    ull* pw = ps2 + warp * (SUB*4);
    #pragma unroll
    for (int p = 0; p < 4; p++) {
        float sa, sb, sc, sd;
        upk2(sa, sb, sq0[p]);
        upk2(sc, sd, sq1[p]);
        float pa = __expf(sa * scale);
        float pb = __expf(sb * scale);
        float pc = __expf(sc * scale);
        float pd = __expf(sd * scale);
        pw[lane*4 + p]      = pk2(pa, pb);
        pw[(lane+32)*4 + p] = pk2(pc, pd);
        lt[2*p]   = pa + pc;
        lt[2*p+1] = pb + pd;
    }
    __syncwarp();

    ull accx[4] = {0,0,0,0}, accy[4] = {0,0,0,0};
    #pragma unroll 4
    for (int j = 0; j < SUB; j++) {
        float2 vv = Vs2[j*32 + lane];
        ull vx = pk2(vv.x, vv.x);
        ull vy = pk2(vv.y, vv.y);
        const ull* pj = &pw[j*4];
        ull pp0 = pj[0], pp1 = pj[1], pp2 = pj[2], pp3 = pj[3];
        ffma2(accx[0], pp0, vx);  ffma2(accy[0], pp0, vy);
        ffma2(accx[1], pp1, vx);  ffma2(accy[1], pp1, vy);
        ffma2(accx[2], pp2, vx);  ffma2(accy[2], pp2, vy);
        ffma2(accx[3], pp3, vx);  ffma2(accy[3], pp3, vy);
    }

    #pragma unroll
    for (int i = 0; i < 8; i++) {
        #pragma unroll
        for (int o = 16; o; o >>= 1) lt[i] += __shfl_xor_sync(0xffffffffu, lt[i], o);
    }
    #pragma unroll
    for (int p = 0; p < 4; p++) {
        float ax0, ax1, ay0, ay1;
        upk2(ax0, ax1, accx[p]);
        upk2(ay0, ay1, accy[p]);
        int u0 = 8*warp + 2*p, u1 = u0 + 1;
        if (u0 < NTOP) {
            size_t pidx = (size_t)(bh*NTOP + u0)*SPLITS + split;
            if (lane == 0) g_pl[pidx] = lt[2*p];
            *(float2*)(g_pacc + pidx*Dn + 2*lane) = make_float2(ax0, ay0);
        }
        if (u1 < NTOP) {
            size_t pidx = (size_t)(bh*NTOP + u1)*SPLITS + split;
            if (lane == 0) g_pl[pidx] = lt[2*p+1];
            *(float2*)(g_pacc + pidx*Dn + 2*lane) = make_float2(ax1, ay1);
        }
    }
}

// ---------------- stage 4: combine splits + scatter ----------------
__global__ __launch_bounds__(256) void k_combine(float* __restrict__ out) {
    int gi = blockIdx.x;
    int bh = gi / NTOP, u = gi % NTOP;
    int b = bh / Hn, h = bh % Hn;
    int tid = threadIdx.x;
    int grp = tid >> 6, d = tid & 63;

    __shared__ float lsh[SPLITS];
    __shared__ float part[4][64];

    if (tid < SPLITS) lsh[tid] = g_pl[(size_t)gi*SPLITS + tid];
    __syncthreads();

    float a = 0.f;
    #pragma unroll
    for (int s16 = 0; s16 < SPLITS/4; s16++)
        a += g_pacc[((size_t)gi*SPLITS + grp*(SPLITS/4) + s16)*Dn + d];
    part[grp][d] = a;
    __syncthreads();

    if (grp == 0) {
        float den = 0.f;
        #pragma unroll
        for (int s = 0; s < SPLITS; s++) den += lsh[s];
        float tot = part[0][d] + part[1][d] + part[2][d] + part[3][d];
        int lq = g_top[bh*NTOP + u];
        out[(((size_t)b*Ln + lq)*Hn + h)*Dn + d] = tot / den;
    }
}

// ---------------- launch: R14 topology (A on origin stream, B + memset on sB) ----------------
extern "C" void kernel_launch(void* const* d_in, const int* in_sizes, int n_in,
                              void* d_out, int out_size) {
    const float* q = (const float*)d_in[0];
    const float* k = (const float*)d_in[1];
    const float* v = (const float*)d_in[2];
    const unsigned* idxraw = (const unsigned*)d_in[4];
    float* out = (float*)d_out;

    static cudaStream_t sB = nullptr;
    static cudaEvent_t evRoot = nullptr, evM = nullptr, evB = nullptr;
    if (sB == nullptr) {
        cudaStreamCreateWithFlags(&sB, cudaStreamNonBlocking);
        cudaEventCreateWithFlags(&evRoot, cudaEventDisableTiming);
        cudaEventCreateWithFlags(&evM,    cudaEventDisableTiming);
        cudaEventCreateWithFlags(&evB,    cudaEventDisableTiming);
    }

    cudaEventRecord(evRoot, 0);
    cudaStreamWaitEvent(sB, evRoot, 0);
    cudaMemsetAsync(d_out, 0, (size_t)out_size * sizeof(float), sB);

    k_init   <<<(Bn*Ln*Hn*Dn/8)/256, 256>>>(k, idxraw);
    k_scoreM <<<(Bn*Ln)/8, 256>>>(q, idxraw);
    cudaEventRecord(evM, 0);
    cudaStreamWaitEvent(sB, evM, 0);

    dim3 gAttn(SPLITS, BHn/2);
    k_cand   <<<BHn/2, 1024>>>(0);
    k_cand   <<<BHn/2, 1024, 0, sB>>>(BHn/2);
    k_rescore<<<(BHn/2)*NCAND*2/8, 256>>>(q, k, idxraw, 0);
    k_rescore<<<(BHn/2)*NCAND*2/8, 256, 0, sB>>>(q, k, idxraw, BHn/2);
    k_sel45  <<<BHn/2, NCAND>>>(0);
    k_sel45  <<<BHn/2, NCAND, 0, sB>>>(BHn/2);
    k_attn   <<<gAttn, ATHREADS>>>(q, k, v, 0);
    k_attn   <<<gAttn, ATHREADS, 0, sB>>>(q, k, v, BHn/2);

    cudaEventRecord(evB, sB);
    cudaStreamWaitEvent(0, evB, 0);
    k_combine<<<BHn*NTOP, 256>>>(out);
}